// round 5
// baseline (speedup 1.0000x reference)
#include <cuda_runtime.h>
#include <cuda_bf16.h>
#include <cstdint>
#include <math.h>

#define BB 128
#define TT 512
#define II 256
#define HH 1024
#define GG 4096
#define CC 1000
#define KTOT 1280
#define NCHUNK 20          // 4 x-chunks + 16 h-chunks of K=64
#define NCTA 128
#define NTHR 512

// SMEM layout (offsets from 128B-aligned dynamic base):
//   Whi [32][1280] bf16 swizzled : 81920
//   Wlo                          : 81920
//   A double buf: 2 x (Ahi 16K + Alo 16K)
#define W_HI 0u
#define W_LO 81920u
#define A_BUF 163840u
#define ABUF_STRIDE 32768u
#define SMEM_DYN (229376 + 256)

// ---------------- device globals (no dynamic alloc) ---------------------------
__device__ __align__(16) __nv_bfloat16 g_Wh[GG * KTOT];
__device__ __align__(16) __nv_bfloat16 g_Wl[GG * KTOT];
__device__ __align__(16) __nv_bfloat16 g_xh[TT * BB * II];   // [t][m][k]
__device__ __align__(16) __nv_bfloat16 g_xl[TT * BB * II];
__device__ __align__(16) __nv_bfloat16 g_hh[2][BB * HH];
__device__ __align__(16) __nv_bfloat16 g_hl[2][BB * HH];
__device__ float g_c[BB * HH];
__device__ float g_bs[GG];
__device__ unsigned g_gc[16];        // per-h-group arrival counters (monotonic)

// ---------------- helpers ------------------------------------------------------
__device__ __forceinline__ uint32_t smem_u32(const void* p) {
    uint32_t a;
    asm("{ .reg .u64 t; cvta.to.shared.u64 t, %1; cvt.u32.u64 %0, t; }" : "=r"(a) : "l"(p));
    return a;
}
__device__ __forceinline__ void cp16(uint32_t saddr, const void* gaddr) {
    asm volatile("cp.async.cg.shared.global [%0], [%1], 16;" :: "r"(saddr), "l"(gaddr) : "memory");
}
__device__ __forceinline__ void ldsm4(uint32_t addr, uint32_t& r0, uint32_t& r1,
                                      uint32_t& r2, uint32_t& r3) {
    asm volatile("ldmatrix.sync.aligned.m8n8.x4.shared.b16 {%0,%1,%2,%3}, [%4];"
                 : "=r"(r0), "=r"(r1), "=r"(r2), "=r"(r3) : "r"(addr));
}
__device__ __forceinline__ void mma16816(float* c, const uint32_t* a, uint32_t b0, uint32_t b1) {
    asm volatile(
        "mma.sync.aligned.m16n8k16.row.col.f32.bf16.bf16.f32 "
        "{%0,%1,%2,%3}, {%4,%5,%6,%7}, {%8,%9}, {%0,%1,%2,%3};"
        : "+f"(c[0]), "+f"(c[1]), "+f"(c[2]), "+f"(c[3])
        : "r"(a[0]), "r"(a[1]), "r"(a[2]), "r"(a[3]), "r"(b0), "r"(b1));
}
__device__ __forceinline__ void gwait(int g, unsigned need) {
    unsigned v;
    while (true) {
        asm volatile("ld.acquire.gpu.global.u32 %0, [%1];"
                     : "=r"(v) : "l"(&g_gc[g]) : "memory");
        if (v >= need) break;
        __nanosleep(32);
    }
}

// ---------------- prep kernels -------------------------------------------------
// Stored row r = nb*32 + hc*4 + q  <->  original row q*H + nb*8 + hc.
__global__ void prep_w(const float* __restrict__ Wih, const float* __restrict__ Whh) {
    int idx = blockIdx.x * blockDim.x + threadIdx.x;
    if (idx >= GG * KTOT) return;
    int r = idx / KTOT, k = idx - r * KTOT;
    int nb = r >> 5, j = r & 31, hc = j >> 2, q = j & 3;
    int orig = q * HH + nb * 8 + hc;
    float v = (k < II) ? Wih[(size_t)orig * II + k] : Whh[(size_t)orig * HH + (k - II)];
    __nv_bfloat16 hi = __float2bfloat16(v);
    g_Wh[idx] = hi;
    g_Wl[idx] = __float2bfloat16(v - __bfloat162float(hi));
}

__global__ void prep_x(const float* __restrict__ x) {
    int idx = blockIdx.x * blockDim.x + threadIdx.x;
    if (idx >= TT * BB * II) return;
    int t = idx / (BB * II);
    int rem = idx - t * (BB * II);
    int m = rem / II, k = rem - m * II;
    float v = x[((size_t)m * TT + t) * II + k];
    __nv_bfloat16 hi = __float2bfloat16(v);
    g_xh[idx] = hi;
    g_xl[idx] = __float2bfloat16(v - __bfloat162float(hi));
}

__global__ void prep_misc(const float* __restrict__ bih, const float* __restrict__ bhh) {
    int i = blockIdx.x * blockDim.x + threadIdx.x;
    if (i < BB * HH) {
        g_hh[0][i] = __float2bfloat16(0.f);
        g_hl[0][i] = __float2bfloat16(0.f);
        g_c[i] = 0.f;
    }
    if (i < GG) g_bs[i] = bih[i] + bhh[i];
    if (i < 16) g_gc[i] = 0u;
}

// ---------------- persistent LSTM kernel ---------------------------------------
// 128 CTAs x 512 thr (16 warps = 4m x 4n). CTA: M=128 (all batch), N=32 gate cols
// = 8 h-cols (gate-interleaved). Warp tile 32x8 -> acc[2 mf][4].
__global__ __launch_bounds__(NTHR, 1) void lstm_persist() {
    extern __shared__ __align__(16) char dsm_raw[];
    const uint32_t dbase = (smem_u32(dsm_raw) + 127) & ~127u;

    const int tid = threadIdx.x;
    const int wid = tid >> 5, lid = tid & 31;
    const int wm = wid & 3, wn = wid >> 2;      // wn 0..3
    const int nb = blockIdx.x;
    const int grp = nb >> 3;                    // this CTA's h-group
    const int mi = lid >> 3, lr = lid & 7;

    // ---- load this CTA's weight slice into SMEM (once) ----
    for (int s = 0; s < 10; s++) {
        int idx = tid + NTHR * s;               // 0..5119
        int row = idx / 160, seg = idx - row * 160;
        size_t go = (size_t)(nb * 32 + row) * KTOT + seg * 8;
        uint32_t so = (uint32_t)row * 2560u + (uint32_t)((seg ^ (row & 7)) << 4);
        cp16(dbase + W_HI + so, g_Wh + go);
        cp16(dbase + W_LO + so, g_Wl + go);
    }
    asm volatile("cp.async.commit_group;" ::: "memory");

    const int lq = lid & 3;
    const bool hasIF = (lq & 1) == 0;
    const int hcl = lq >> 1;

#pragma unroll 1
    for (int t = 0; t < TT; t++) {
        const __nv_bfloat16* __restrict__ hsh = g_hh[t & 1];
        const __nv_bfloat16* __restrict__ hsl = g_hl[t & 1];
        const __nv_bfloat16* __restrict__ xsh = g_xh + (size_t)t * (BB * II);
        const __nv_bfloat16* __restrict__ xsl = g_xl + (size_t)t * (BB * II);

        // rotated chunk order: x chunks first, then h chunks starting at own group
        auto ckof = [&](int i) -> int {
            return (i < 4) ? i : 4 + ((grp + (i - 4)) & 15);
        };
        // A chunk loader (2048 cp16 across 512 threads)
        auto load_chunk = [&](int parity, int ck) {
            const uint32_t bofs = A_BUF + (uint32_t)parity * ABUF_STRIDE;
            const int k0 = ck * 64;
            const bool xreg = (ck < 4);
#pragma unroll
            for (int s = 0; s < 4; s++) {
                int idx = tid + NTHR * s;       // 0..2047
                int reg = idx >> 10;            // 0 hi, 1 lo
                int w = idx & 1023;
                int row = w >> 3, seg = w & 7;
                uint32_t sa = dbase + bofs + (uint32_t)reg * 16384u
                            + (uint32_t)row * 128u + (uint32_t)((seg ^ (row & 7)) << 4);
                const __nv_bfloat16* g;
                if (xreg) g = (reg ? xsl : xsh) + (size_t)row * II + k0 + seg * 8;
                else      g = (reg ? hsl : hsh) + (size_t)row * HH + (k0 - II) + seg * 8;
                cp16(sa, g);
            }
            asm volatile("cp.async.commit_group;" ::: "memory");
        };

        float acc[2][4];
#pragma unroll
        for (int a = 0; a < 2; a++)
#pragma unroll
            for (int i = 0; i < 4; i++) acc[a][i] = 0.f;

        load_chunk(0, ckof(0));
        load_chunk(1, ckof(1));

#pragma unroll 1
        for (int i = 0; i < NCHUNK; i++) {
            if (i + 1 < NCHUNK) asm volatile("cp.async.wait_group 1;" ::: "memory");
            else                asm volatile("cp.async.wait_group 0;" ::: "memory");
            __syncthreads();

            const int ck = ckof(i);
            const uint32_t abase = dbase + A_BUF + (uint32_t)(i & 1) * ABUF_STRIDE;
            const uint32_t bbase = dbase + W_HI + (uint32_t)(wn * 8 + lr) * 2560u;
            const int bxor = lr & 7;

#pragma unroll
            for (int p = 0; p < 2; p++) {
                // B frags for ks = 2p, 2p+1 (resident W, hi & lo)
                uint32_t bh[4], bl[4];
                {
                    int kseg = ck * 8 + p * 4 + mi;
                    uint32_t bd = bbase + (uint32_t)((kseg ^ bxor) << 4);
                    ldsm4(bd, bh[0], bh[1], bh[2], bh[3]);
                    ldsm4(bd + (W_LO - W_HI), bl[0], bl[1], bl[2], bl[3]);
                }
#pragma unroll
                for (int q = 0; q < 2; q++) {
                    const int ks = p * 2 + q;
                    uint32_t ah[2][4], al[2][4];
#pragma unroll
                    for (int mf = 0; mf < 2; mf++) {
                        int arow = wm * 32 + mf * 16 + ((mi & 1) << 3) + lr;
                        int ksega = ks * 2 + (mi >> 1);
                        uint32_t ad = abase + (uint32_t)arow * 128u
                                    + (uint32_t)((ksega ^ (arow & 7)) << 4);
                        ldsm4(ad, ah[mf][0], ah[mf][1], ah[mf][2], ah[mf][3]);
                        ldsm4(ad + 16384u, al[mf][0], al[mf][1], al[mf][2], al[mf][3]);
                    }
#pragma unroll
                    for (int mf = 0; mf < 2; mf++) {
                        mma16816(acc[mf], ah[mf], bh[q * 2], bh[q * 2 + 1]);
                        mma16816(acc[mf], ah[mf], bl[q * 2], bl[q * 2 + 1]);
                        mma16816(acc[mf], al[mf], bh[q * 2], bh[q * 2 + 1]);
                    }
                }
            }
            __syncthreads();
            if (i + 2 < NCHUNK) {
                int c2 = ckof(i + 2);
                if (c2 >= 4) gwait(c2 - 4, 8u * (unsigned)t);   // h(t) group ready?
                load_chunk(i & 1, c2);
            }
        }

        // ---- epilogue: bias + LSTM update, write h(t+1) ----
        __nv_bfloat16* __restrict__ hh_o = g_hh[(t + 1) & 1];
        __nv_bfloat16* __restrict__ hl_o = g_hl[(t + 1) & 1];
        const int nglob = nb * 8 + wn * 2 + hcl;
        const float bias0 = g_bs[(hasIF ? 0 : 2) * HH + nglob];
        const float bias1 = g_bs[(hasIF ? 1 : 3) * HH + nglob];
#pragma unroll
        for (int mf = 0; mf < 2; mf++) {
            const int rbase = wm * 32 + mf * 16 + (lid >> 2);
            float d0 = acc[mf][0] + bias0;
            float d1 = acc[mf][1] + bias1;
            float d2 = acc[mf][2] + bias0;
            float d3 = acc[mf][3] + bias1;
            float e0 = __shfl_xor_sync(0xFFFFFFFFu, d0, 1);
            float e1 = __shfl_xor_sync(0xFFFFFFFFu, d1, 1);
            float e2 = __shfl_xor_sync(0xFFFFFFFFu, d2, 1);
            float e3 = __shfl_xor_sync(0xFFFFFFFFu, d3, 1);
            if (hasIF) {
#pragma unroll
                for (int r = 0; r < 2; r++) {
                    float gi = r ? d2 : d0, gf = r ? d3 : d1;
                    float gg = r ? e2 : e0, go = r ? e3 : e1;
                    float iv = 1.f / (1.f + expf(-gi));
                    float fv = 1.f / (1.f + expf(-gf));
                    float gv = tanhf(gg);
                    float ov = 1.f / (1.f + expf(-go));
                    size_t idx = (size_t)(rbase + r * 8) * HH + nglob;
                    float cn = fv * g_c[idx] + iv * gv;
                    g_c[idx] = cn;
                    float hv = ov * tanhf(cn);
                    __nv_bfloat16 hi = __float2bfloat16(hv);
                    hh_o[idx] = hi;
                    hl_o[idx] = __float2bfloat16(hv - __bfloat162float(hi));
                }
            }
        }
        __threadfence();
        __syncthreads();
        if (tid == 0) {
            unsigned dummy;
            asm volatile("atom.release.gpu.global.add.u32 %0, [%1], 1;"
                         : "=r"(dummy) : "l"(&g_gc[grp]) : "memory");
        }
    }
}

// ---------------- final FC ------------------------------------------------------
__global__ __launch_bounds__(256) void fc_kernel(
    const float* __restrict__ fcW, const float* __restrict__ fcb, float* __restrict__ out) {
    int w = blockIdx.x * 8 + (threadIdx.x >> 5);
    int lane = threadIdx.x & 31;
    if (w >= BB * CC) return;
    int b = w / CC, c = w - b * CC;
    const __nv_bfloat16* __restrict__ hh = g_hh[0] + (size_t)b * HH;   // TT even
    const __nv_bfloat16* __restrict__ hl = g_hl[0] + (size_t)b * HH;
    const float* __restrict__ wr = fcW + (size_t)c * HH;
    float s = 0.f;
#pragma unroll 4
    for (int k = lane; k < HH; k += 32)
        s += (__bfloat162float(hh[k]) + __bfloat162float(hl[k])) * wr[k];
#pragma unroll
    for (int o = 16; o; o >>= 1) s += __shfl_down_sync(0xFFFFFFFFu, s, o);
    if (lane == 0) out[b * CC + c] = s + fcb[c];
}

extern "C" void kernel_launch(void* const* d_in, const int* in_sizes, int n_in,
                              void* d_out, int out_size) {
    const float* x   = (const float*)d_in[0];
    const float* Wih = (const float*)d_in[1];
    const float* Whh = (const float*)d_in[2];
    const float* bih = (const float*)d_in[3];
    const float* bhh = (const float*)d_in[4];
    const float* fcW = (const float*)d_in[5];
    const float* fcb = (const float*)d_in[6];
    float* out = (float*)d_out;

    cudaFuncSetAttribute(lstm_persist, cudaFuncAttributeMaxDynamicSharedMemorySize, SMEM_DYN);

    prep_w<<<(GG * KTOT + 255) / 256, 256>>>(Wih, Whh);
    prep_x<<<(TT * BB * II + 255) / 256, 256>>>(x);
    prep_misc<<<(BB * HH + 255) / 256, 256>>>(bih, bhh);
    lstm_persist<<<NCTA, NTHR, SMEM_DYN>>>();
    fc_kernel<<<(BB * CC + 7) / 8, 256>>>(fcW, fcb, out);
}

// round 6
// speedup vs baseline: 1.2392x; 1.2392x over previous
#include <cuda_runtime.h>
#include <cuda_bf16.h>
#include <cstdint>
#include <math.h>

#define BB 128
#define TT 512
#define II 256
#define HH 1024
#define GG 4096
#define CC 1000
#define KTOT 1280
#define NCHUNK 20          // 4 x-chunks then 16 h-chunks of K=64
#define NCTA 128
#define NTHR 512

// SMEM layout (offsets from 128B-aligned dynamic base):
//   Whi [32][1280] bf16 swizzled : 81920
//   Wlo                          : 81920
//   A double buf: 2 x (Ahi 16K + Alo 16K)
#define W_HI 0u
#define W_LO 81920u
#define A_BUF 163840u
#define ABUF_STRIDE 32768u
#define SMEM_DYN (229376 + 256)

// ---------------- device globals (no dynamic alloc) ---------------------------
__device__ __align__(16) __nv_bfloat16 g_Wh[GG * KTOT];
__device__ __align__(16) __nv_bfloat16 g_Wl[GG * KTOT];
__device__ __align__(16) __nv_bfloat16 g_xh[TT * BB * II];   // [t][m][k]
__device__ __align__(16) __nv_bfloat16 g_xl[TT * BB * II];
__device__ __align__(16) __nv_bfloat16 g_hh[2][BB * HH];
__device__ __align__(16) __nv_bfloat16 g_hl[2][BB * HH];
__device__ float g_c[BB * HH];
__device__ float g_bs[GG];
__device__ unsigned g_bar_cnt;
__device__ unsigned g_bar_flag;

// ---------------- helpers ------------------------------------------------------
__device__ __forceinline__ uint32_t smem_u32(const void* p) {
    uint32_t a;
    asm("{ .reg .u64 t; cvta.to.shared.u64 t, %1; cvt.u32.u64 %0, t; }" : "=r"(a) : "l"(p));
    return a;
}
__device__ __forceinline__ void cp16(uint32_t saddr, const void* gaddr) {
    asm volatile("cp.async.cg.shared.global [%0], [%1], 16;" :: "r"(saddr), "l"(gaddr) : "memory");
}
__device__ __forceinline__ void ldsm4(uint32_t addr, uint32_t& r0, uint32_t& r1,
                                      uint32_t& r2, uint32_t& r3) {
    asm volatile("ldmatrix.sync.aligned.m8n8.x4.shared.b16 {%0,%1,%2,%3}, [%4];"
                 : "=r"(r0), "=r"(r1), "=r"(r2), "=r"(r3) : "r"(addr));
}
__device__ __forceinline__ void mma16816(float* c, const uint32_t* a, uint32_t b0, uint32_t b1) {
    asm volatile(
        "mma.sync.aligned.m16n8k16.row.col.f32.bf16.bf16.f32 "
        "{%0,%1,%2,%3}, {%4,%5,%6,%7}, {%8,%9}, {%0,%1,%2,%3};"
        : "+f"(c[0]), "+f"(c[1]), "+f"(c[2]), "+f"(c[3])
        : "r"(a[0]), "r"(a[1]), "r"(a[2]), "r"(a[3]), "r"(b0), "r"(b1));
}

// ---------------- prep kernels -------------------------------------------------
// Stored row r = nb*32 + hc*4 + q  <->  original row q*H + nb*8 + hc.
__global__ void prep_w(const float* __restrict__ Wih, const float* __restrict__ Whh) {
    int idx = blockIdx.x * blockDim.x + threadIdx.x;
    if (idx >= GG * KTOT) return;
    int r = idx / KTOT, k = idx - r * KTOT;
    int nb = r >> 5, j = r & 31, hc = j >> 2, q = j & 3;
    int orig = q * HH + nb * 8 + hc;
    float v = (k < II) ? Wih[(size_t)orig * II + k] : Whh[(size_t)orig * HH + (k - II)];
    __nv_bfloat16 hi = __float2bfloat16(v);
    g_Wh[idx] = hi;
    g_Wl[idx] = __float2bfloat16(v - __bfloat162float(hi));
}

__global__ void prep_x(const float* __restrict__ x) {
    int idx = blockIdx.x * blockDim.x + threadIdx.x;
    if (idx >= TT * BB * II) return;
    int t = idx / (BB * II);
    int rem = idx - t * (BB * II);
    int m = rem / II, k = rem - m * II;
    float v = x[((size_t)m * TT + t) * II + k];
    __nv_bfloat16 hi = __float2bfloat16(v);
    g_xh[idx] = hi;
    g_xl[idx] = __float2bfloat16(v - __bfloat162float(hi));
}

__global__ void prep_misc(const float* __restrict__ bih, const float* __restrict__ bhh) {
    int i = blockIdx.x * blockDim.x + threadIdx.x;
    if (i < BB * HH) {
        g_hh[0][i] = __float2bfloat16(0.f);
        g_hl[0][i] = __float2bfloat16(0.f);
        g_c[i] = 0.f;
    }
    if (i < GG) g_bs[i] = bih[i] + bhh[i];
    if (i == 0) { g_bar_cnt = 0u; g_bar_flag = 0u; }
}

// ---------------- grid barrier (all 128 CTAs resident, one wave) ---------------
__device__ __forceinline__ void bar_arrive(unsigned step) {
    if (threadIdx.x == 0) {
        unsigned v;
        asm volatile("atom.release.gpu.global.add.u32 %0, [%1], 1;"
                     : "=r"(v) : "l"(&g_bar_cnt) : "memory");
        if (v == NCTA * (step + 1) - 1) {
            asm volatile("st.release.gpu.global.u32 [%0], %1;"
                         :: "l"(&g_bar_flag), "r"(step + 1) : "memory");
        }
    }
}
__device__ __forceinline__ void bar_wait(unsigned step) {   // wait flag >= step
    if (threadIdx.x == 0) {
        unsigned f;
        while (true) {
            asm volatile("ld.acquire.gpu.global.u32 %0, [%1];"
                         : "=r"(f) : "l"(&g_bar_flag) : "memory");
            if (f >= step) break;
            __nanosleep(64);
        }
    }
    __syncthreads();
}

// ---------------- persistent LSTM kernel ---------------------------------------
// 128 CTAs x 512 thr (16 warps = 8m x 2n). CTA: M=128, N=32 gate cols = 8 h-cols.
// Warp tile 16x16 -> acc[2 nf][4].
__global__ __launch_bounds__(NTHR, 1) void lstm_persist() {
    extern __shared__ __align__(16) char dsm_raw[];
    const uint32_t dbase = (smem_u32(dsm_raw) + 127) & ~127u;

    const int tid = threadIdx.x;
    const int wid = tid >> 5, lid = tid & 31;
    const int wm = wid >> 1, wn = wid & 1;      // 8 m-groups x 2 n-groups
    const int nb = blockIdx.x;
    const int mi = lid >> 3, lr = lid & 7;

    // ---- load this CTA's weight slice into SMEM (once) ----
    for (int s = 0; s < 10; s++) {
        int idx = tid + NTHR * s;               // 0..5119
        int row = idx / 160, seg = idx - row * 160;
        size_t go = (size_t)(nb * 32 + row) * KTOT + seg * 8;
        uint32_t so = (uint32_t)row * 2560u + (uint32_t)((seg ^ (row & 7)) << 4);
        cp16(dbase + W_HI + so, g_Wh + go);
        cp16(dbase + W_LO + so, g_Wl + go);
    }
    asm volatile("cp.async.commit_group;" ::: "memory");

    const int lq = lid & 3;
    const bool hasIF = (lq & 1) == 0;
    const int hcl = lq >> 1;

    // lane-fixed ldsm addressing pieces
    const int arow = wm * 16 + ((mi & 1) << 3) + lr;
    const uint32_t aoff = (uint32_t)arow * 128u;
    const int axor = arow & 7;
    const int brow = wn * 16 + ((mi >> 1) << 3) + lr;
    const uint32_t bbase0 = dbase + W_HI + (uint32_t)brow * 2560u;
    const int bxor = brow & 7;

#pragma unroll 1
    for (int t = 0; t < TT; t++) {
        const __nv_bfloat16* __restrict__ hsh = g_hh[t & 1];
        const __nv_bfloat16* __restrict__ hsl = g_hl[t & 1];
        const __nv_bfloat16* __restrict__ xsh = g_xh + (size_t)t * (BB * II);
        const __nv_bfloat16* __restrict__ xsl = g_xl + (size_t)t * (BB * II);

        // A chunk loader: 2048 cp16 over 512 threads
        auto load_chunk = [&](int kc) {
            const uint32_t bofs = A_BUF + (uint32_t)(kc & 1) * ABUF_STRIDE;
            const int k0 = kc * 64;
            const bool xreg = (kc < 4);
#pragma unroll
            for (int s = 0; s < 4; s++) {
                int idx = tid + NTHR * s;       // 0..2047
                int reg = idx >> 10;            // 0 hi, 1 lo
                int w = idx & 1023;
                int row = w >> 3, seg = w & 7;
                uint32_t sa = dbase + bofs + (uint32_t)reg * 16384u
                            + (uint32_t)row * 128u + (uint32_t)((seg ^ (row & 7)) << 4);
                const __nv_bfloat16* g;
                if (xreg) g = (reg ? xsl : xsh) + (size_t)row * II + k0 + seg * 8;
                else      g = (reg ? hsl : hsh) + (size_t)row * HH + (k0 - II) + seg * 8;
                cp16(sa, g);
            }
            asm volatile("cp.async.commit_group;" ::: "memory");
        };

        float acc[2][4];
#pragma unroll
        for (int a = 0; a < 2; a++)
#pragma unroll
            for (int i = 0; i < 4; i++) acc[a][i] = 0.f;

        load_chunk(0);
        load_chunk(1);

#pragma unroll 1
        for (int kc = 0; kc < NCHUNK; kc++) {
            if (kc + 1 < NCHUNK) asm volatile("cp.async.wait_group 1;" ::: "memory");
            else                 asm volatile("cp.async.wait_group 0;" ::: "memory");
            __syncthreads();

            const uint32_t abase = dbase + A_BUF + (uint32_t)(kc & 1) * ABUF_STRIDE;

#pragma unroll
            for (int ks = 0; ks < 4; ks++) {
                // A frag m16k16 (hi & lo)
                uint32_t ah[4], al[4];
                {
                    int ksega = ks * 2 + (mi >> 1);
                    uint32_t ad = abase + aoff + (uint32_t)((ksega ^ axor) << 4);
                    ldsm4(ad, ah[0], ah[1], ah[2], ah[3]);
                    ldsm4(ad + 16384u, al[0], al[1], al[2], al[3]);
                }
                // B frag n16k16 (hi & lo) from resident W
                uint32_t bh[4], bl[4];
                {
                    int kseg = kc * 8 + ks * 2 + (mi & 1);
                    uint32_t bd = bbase0 + (uint32_t)((kseg ^ bxor) << 4);
                    ldsm4(bd, bh[0], bh[1], bh[2], bh[3]);
                    ldsm4(bd + (W_LO - W_HI), bl[0], bl[1], bl[2], bl[3]);
                }
#pragma unroll
                for (int nf = 0; nf < 2; nf++) {
                    mma16816(acc[nf], ah, bh[nf * 2], bh[nf * 2 + 1]);
                    mma16816(acc[nf], ah, bl[nf * 2], bl[nf * 2 + 1]);
                    mma16816(acc[nf], al, bh[nf * 2], bh[nf * 2 + 1]);
                }
            }
            __syncthreads();
            if (kc + 2 < NCHUNK) {
                if (kc + 2 == 4) bar_wait((unsigned)t);   // h(t) ready before first h chunk
                load_chunk(kc + 2);
            }
        }

        // ---- epilogue: bias + LSTM update, write h(t+1) ----
        __nv_bfloat16* __restrict__ hh_o = g_hh[(t + 1) & 1];
        __nv_bfloat16* __restrict__ hl_o = g_hl[(t + 1) & 1];
        const int rbase = wm * 16 + (lid >> 2);
#pragma unroll
        for (int nf = 0; nf < 2; nf++) {
            const int nglob = nb * 8 + wn * 4 + nf * 2 + hcl;
            const float bias0 = g_bs[(hasIF ? 0 : 2) * HH + nglob];
            const float bias1 = g_bs[(hasIF ? 1 : 3) * HH + nglob];
            float d0 = acc[nf][0] + bias0;
            float d1 = acc[nf][1] + bias1;
            float d2 = acc[nf][2] + bias0;
            float d3 = acc[nf][3] + bias1;
            float e0 = __shfl_xor_sync(0xFFFFFFFFu, d0, 1);
            float e1 = __shfl_xor_sync(0xFFFFFFFFu, d1, 1);
            float e2 = __shfl_xor_sync(0xFFFFFFFFu, d2, 1);
            float e3 = __shfl_xor_sync(0xFFFFFFFFu, d3, 1);
            if (hasIF) {
#pragma unroll
                for (int r = 0; r < 2; r++) {
                    float gi = r ? d2 : d0, gf = r ? d3 : d1;
                    float gg = r ? e2 : e0, go = r ? e3 : e1;
                    float iv = 1.f / (1.f + expf(-gi));
                    float fv = 1.f / (1.f + expf(-gf));
                    float gv = tanhf(gg);
                    float ov = 1.f / (1.f + expf(-go));
                    size_t idx = (size_t)(rbase + r * 8) * HH + nglob;
                    float cn = fv * g_c[idx] + iv * gv;
                    g_c[idx] = cn;
                    float hv = ov * tanhf(cn);
                    __nv_bfloat16 hi = __float2bfloat16(hv);
                    hh_o[idx] = hi;
                    hl_o[idx] = __float2bfloat16(hv - __bfloat162float(hi));
                }
            }
        }
        __threadfence();
        __syncthreads();
        bar_arrive((unsigned)t);
    }
}

// ---------------- final FC ------------------------------------------------------
__global__ __launch_bounds__(256) void fc_kernel(
    const float* __restrict__ fcW, const float* __restrict__ fcb, float* __restrict__ out) {
    int w = blockIdx.x * 8 + (threadIdx.x >> 5);
    int lane = threadIdx.x & 31;
    if (w >= BB * CC) return;
    int b = w / CC, c = w - b * CC;
    const __nv_bfloat16* __restrict__ hh = g_hh[0] + (size_t)b * HH;   // TT even
    const __nv_bfloat16* __restrict__ hl = g_hl[0] + (size_t)b * HH;
    const float* __restrict__ wr = fcW + (size_t)c * HH;
    float s = 0.f;
#pragma unroll 4
    for (int k = lane; k < HH; k += 32)
        s += (__bfloat162float(hh[k]) + __bfloat162float(hl[k])) * wr[k];
#pragma unroll
    for (int o = 16; o; o >>= 1) s += __shfl_down_sync(0xFFFFFFFFu, s, o);
    if (lane == 0) out[b * CC + c] = s + fcb[c];
}

extern "C" void kernel_launch(void* const* d_in, const int* in_sizes, int n_in,
                              void* d_out, int out_size) {
    const float* x   = (const float*)d_in[0];
    const float* Wih = (const float*)d_in[1];
    const float* Whh = (const float*)d_in[2];
    const float* bih = (const float*)d_in[3];
    const float* bhh = (const float*)d_in[4];
    const float* fcW = (const float*)d_in[5];
    const float* fcb = (const float*)d_in[6];
    float* out = (float*)d_out;

    cudaFuncSetAttribute(lstm_persist, cudaFuncAttributeMaxDynamicSharedMemorySize, SMEM_DYN);

    prep_w<<<(GG * KTOT + 255) / 256, 256>>>(Wih, Whh);
    prep_x<<<(TT * BB * II + 255) / 256, 256>>>(x);
    prep_misc<<<(BB * HH + 255) / 256, 256>>>(bih, bhh);
    lstm_persist<<<NCTA, NTHR, SMEM_DYN>>>();
    fc_kernel<<<(BB * CC + 7) / 8, 256>>>(fcW, fcb, out);
}

// round 7
// speedup vs baseline: 1.6096x; 1.2989x over previous
#include <cuda_runtime.h>
#include <cuda_fp16.h>
#include <cstdint>
#include <math.h>

#define BB 128
#define TT 512
#define II 256
#define HH 1024
#define GG 4096
#define CC 1000
#define KTOT 1280
#define NCHUNK 10          // K chunks of 128: chunks 0,1 = x, 2..9 = h
#define NCTA 128
#define NTHR 512

// SMEM layout (offsets from 128B-aligned dynamic base):
//   Whi [32][1280] fp16 swizzled, 2560B rows : 81920
//   A double buf: 2 x 64KB; each buf = [sub0: hi 16K | lo 16K][sub1: hi | lo]
#define W_HI 0u
#define A_BUF 81920u
#define ABUF_STRIDE 65536u
#define SMEM_DYN (81920 + 131072 + 256)

// ---------------- device globals (no dynamic alloc) ---------------------------
__device__ __align__(16) __half g_Wh[GG * KTOT];            // weights hi, permuted
__device__ __align__(16) __half g_xh[TT * BB * II];         // x hi, [t][m][k]
__device__ __align__(16) __half g_xl[TT * BB * II];         // x lo
__device__ __align__(16) __half g_hh[2][BB * HH];           // h hi ping-pong
__device__ __align__(16) __half g_hl[2][BB * HH];           // h lo ping-pong
__device__ float g_c[BB * HH];
__device__ float g_bs[GG];
__device__ unsigned g_bar_cnt;
__device__ unsigned g_bar_flag;

// ---------------- helpers ------------------------------------------------------
__device__ __forceinline__ uint32_t smem_u32(const void* p) {
    uint32_t a;
    asm("{ .reg .u64 t; cvta.to.shared.u64 t, %1; cvt.u32.u64 %0, t; }" : "=r"(a) : "l"(p));
    return a;
}
__device__ __forceinline__ void cp16(uint32_t saddr, const void* gaddr) {
    asm volatile("cp.async.cg.shared.global [%0], [%1], 16;" :: "r"(saddr), "l"(gaddr) : "memory");
}
__device__ __forceinline__ void ldsm4(uint32_t addr, uint32_t& r0, uint32_t& r1,
                                      uint32_t& r2, uint32_t& r3) {
    asm volatile("ldmatrix.sync.aligned.m8n8.x4.shared.b16 {%0,%1,%2,%3}, [%4];"
                 : "=r"(r0), "=r"(r1), "=r"(r2), "=r"(r3) : "r"(addr));
}
__device__ __forceinline__ void mma16816(float* c, const uint32_t* a, uint32_t b0, uint32_t b1) {
    asm volatile(
        "mma.sync.aligned.m16n8k16.row.col.f32.f16.f16.f32 "
        "{%0,%1,%2,%3}, {%4,%5,%6,%7}, {%8,%9}, {%0,%1,%2,%3};"
        : "+f"(c[0]), "+f"(c[1]), "+f"(c[2]), "+f"(c[3])
        : "r"(a[0]), "r"(a[1]), "r"(a[2]), "r"(a[3]), "r"(b0), "r"(b1));
}

// ---------------- prep kernels -------------------------------------------------
// Stored row r = nb*32 + hc*4 + q  <->  original row q*H + nb*8 + hc.
__global__ void prep_w(const float* __restrict__ Wih, const float* __restrict__ Whh) {
    int idx = blockIdx.x * blockDim.x + threadIdx.x;
    if (idx >= GG * KTOT) return;
    int r = idx / KTOT, k = idx - r * KTOT;
    int nb = r >> 5, j = r & 31, hc = j >> 2, q = j & 3;
    int orig = q * HH + nb * 8 + hc;
    float v = (k < II) ? Wih[(size_t)orig * II + k] : Whh[(size_t)orig * HH + (k - II)];
    g_Wh[idx] = __float2half_rn(v);
}

__global__ void prep_x(const float* __restrict__ x) {
    int idx = blockIdx.x * blockDim.x + threadIdx.x;
    if (idx >= TT * BB * II) return;
    int t = idx / (BB * II);
    int rem = idx - t * (BB * II);
    int m = rem / II, k = rem - m * II;
    float v = x[((size_t)m * TT + t) * II + k];
    __half hi = __float2half_rn(v);
    g_xh[idx] = hi;
    g_xl[idx] = __float2half_rn(v - __half2float(hi));
}

__global__ void prep_misc(const float* __restrict__ bih, const float* __restrict__ bhh) {
    int i = blockIdx.x * blockDim.x + threadIdx.x;
    if (i < BB * HH) {
        g_hh[0][i] = __float2half_rn(0.f);
        g_hl[0][i] = __float2half_rn(0.f);
        g_c[i] = 0.f;
    }
    if (i < GG) g_bs[i] = bih[i] + bhh[i];
    if (i == 0) { g_bar_cnt = 0u; g_bar_flag = 0u; }
}

// ---------------- grid barrier (all 128 CTAs resident, one wave) ---------------
__device__ __forceinline__ void bar_arrive(unsigned step) {
    if (threadIdx.x == 0) {
        unsigned v;
        asm volatile("atom.release.gpu.global.add.u32 %0, [%1], 1;"
                     : "=r"(v) : "l"(&g_bar_cnt) : "memory");
        if (v == NCTA * (step + 1) - 1) {
            asm volatile("st.release.gpu.global.u32 [%0], %1;"
                         :: "l"(&g_bar_flag), "r"(step + 1) : "memory");
        }
    }
}
__device__ __forceinline__ void bar_wait(unsigned step) {   // wait flag >= step
    if (threadIdx.x == 0) {
        unsigned f;
        while (true) {
            asm volatile("ld.acquire.gpu.global.u32 %0, [%1];"
                         : "=r"(f) : "l"(&g_bar_flag) : "memory");
            if (f >= step) break;
            __nanosleep(64);
        }
    }
    __syncthreads();
}

// ---------------- persistent LSTM kernel ---------------------------------------
// 128 CTAs x 512 thr (16 warps = 8m x 2n). CTA: M=128, N=32 gate cols = 8 h-cols.
// Warp tile 16x16 -> acc[2 nf][4]. fp16 2-pass: D = (Ahi + Alo) x Whi.
__global__ __launch_bounds__(NTHR, 1) void lstm_persist() {
    extern __shared__ __align__(16) char dsm_raw[];
    const uint32_t dbase = (smem_u32(dsm_raw) + 127) & ~127u;

    const int tid = threadIdx.x;
    const int wid = tid >> 5, lid = tid & 31;
    const int wm = wid >> 1, wn = wid & 1;      // 8 m-groups x 2 n-groups
    const int nb = blockIdx.x;
    const int mi = lid >> 3, lr = lid & 7;

    // ---- load this CTA's weight slice (hi only) into SMEM once ----
    for (int s = 0; s < 10; s++) {
        int idx = tid + NTHR * s;               // 0..5119
        int row = idx / 160, seg = idx - row * 160;
        size_t go = (size_t)(nb * 32 + row) * KTOT + seg * 8;
        uint32_t so = (uint32_t)row * 2560u + (uint32_t)((seg ^ (row & 7)) << 4);
        cp16(dbase + W_HI + so, g_Wh + go);
    }
    asm volatile("cp.async.commit_group;" ::: "memory");

    const int lq = lid & 3;
    const bool hasIF = (lq & 1) == 0;
    const int hcl = lq >> 1;

    // lane-fixed ldsm addressing pieces
    const int arow = wm * 16 + ((mi & 1) << 3) + lr;
    const uint32_t aoff = (uint32_t)arow * 128u;
    const int axor = arow & 7;
    const int brow = wn * 16 + ((mi >> 1) << 3) + lr;
    const uint32_t bbase0 = dbase + W_HI + (uint32_t)brow * 2560u;
    const int bxor = brow & 7;

#pragma unroll 1
    for (int t = 0; t < TT; t++) {
        const __half* __restrict__ hsh = g_hh[t & 1];
        const __half* __restrict__ hsl = g_hl[t & 1];
        const __half* __restrict__ xsh = g_xh + (size_t)t * (BB * II);
        const __half* __restrict__ xsl = g_xl + (size_t)t * (BB * II);

        // A chunk loader: K=128 chunk = 4096 cp16 over 512 threads (8 each)
        auto load_chunk = [&](int kc) {
            const uint32_t bofs = A_BUF + (uint32_t)(kc & 1) * ABUF_STRIDE;
            const int k0 = kc * 128;
            const bool xreg = (kc < 2);
#pragma unroll
            for (int s = 0; s < 8; s++) {
                int idx = tid + NTHR * s;       // 0..4095
                int reg = idx >> 11;            // 0 hi, 1 lo
                int w = idx & 2047;
                int row = w >> 4, seg = w & 15; // seg 0..15 (16B units of K)
                uint32_t sa = dbase + bofs + (uint32_t)(seg >> 3) * 32768u
                            + (uint32_t)reg * 16384u
                            + (uint32_t)row * 128u
                            + (uint32_t)(((seg & 7) ^ (row & 7)) << 4);
                const __half* g;
                if (xreg) g = (reg ? xsl : xsh) + (size_t)row * II + k0 + seg * 8;
                else      g = (reg ? hsl : hsh) + (size_t)row * HH + (k0 - II) + seg * 8;
                cp16(sa, g);
            }
            asm volatile("cp.async.commit_group;" ::: "memory");
        };

        float acc[2][4];
#pragma unroll
        for (int a = 0; a < 2; a++)
#pragma unroll
            for (int i = 0; i < 4; i++) acc[a][i] = 0.f;

        load_chunk(0);          // x
        load_chunk(1);          // x

#pragma unroll 1
        for (int kc = 0; kc < NCHUNK; kc++) {
            if (kc + 1 < NCHUNK) asm volatile("cp.async.wait_group 1;" ::: "memory");
            else                 asm volatile("cp.async.wait_group 0;" ::: "memory");
            __syncthreads();

            const uint32_t abase = dbase + A_BUF + (uint32_t)(kc & 1) * ABUF_STRIDE;

#pragma unroll
            for (int ks = 0; ks < 8; ks++) {
                // A frag m16k16 (hi & lo)
                uint32_t ah[4], al[4];
                {
                    int ksega = (ks & 3) * 2 + (mi >> 1);
                    uint32_t ad = abase + (uint32_t)(ks >> 2) * 32768u + aoff
                                + (uint32_t)((ksega ^ axor) << 4);
                    ldsm4(ad, ah[0], ah[1], ah[2], ah[3]);
                    ldsm4(ad + 16384u, al[0], al[1], al[2], al[3]);
                }
                // B frag n16k16 (hi only) from resident W
                uint32_t bh[4];
                {
                    int kseg = kc * 16 + ks * 2 + (mi & 1);
                    uint32_t bd = bbase0 + (uint32_t)((kseg ^ bxor) << 4);
                    ldsm4(bd, bh[0], bh[1], bh[2], bh[3]);
                }
                // interleave accumulators to space same-acc dependencies
                mma16816(acc[0], ah, bh[0], bh[1]);
                mma16816(acc[1], ah, bh[2], bh[3]);
                mma16816(acc[0], al, bh[0], bh[1]);
                mma16816(acc[1], al, bh[2], bh[3]);
            }
            __syncthreads();
            if (kc + 2 < NCHUNK) {
                if (kc + 2 == 2) bar_wait((unsigned)t);   // h(t) ready before 1st h chunk
                load_chunk(kc + 2);
            }
        }

        // ---- epilogue: bias + LSTM update, write h(t+1) as fp16 hi/lo ----
        __half* __restrict__ hh_o = g_hh[(t + 1) & 1];
        __half* __restrict__ hl_o = g_hl[(t + 1) & 1];
        const int rbase = wm * 16 + (lid >> 2);
#pragma unroll
        for (int nf = 0; nf < 2; nf++) {
            const int nglob = nb * 8 + wn * 4 + nf * 2 + hcl;
            const float bias0 = g_bs[(hasIF ? 0 : 2) * HH + nglob];
            const float bias1 = g_bs[(hasIF ? 1 : 3) * HH + nglob];
            float d0 = acc[nf][0] + bias0;
            float d1 = acc[nf][1] + bias1;
            float d2 = acc[nf][2] + bias0;
            float d3 = acc[nf][3] + bias1;
            float e0 = __shfl_xor_sync(0xFFFFFFFFu, d0, 1);
            float e1 = __shfl_xor_sync(0xFFFFFFFFu, d1, 1);
            float e2 = __shfl_xor_sync(0xFFFFFFFFu, d2, 1);
            float e3 = __shfl_xor_sync(0xFFFFFFFFu, d3, 1);
            if (hasIF) {
#pragma unroll
                for (int r = 0; r < 2; r++) {
                    float gi = r ? d2 : d0, gf = r ? d3 : d1;
                    float gg = r ? e2 : e0, go = r ? e3 : e1;
                    float iv = 1.f / (1.f + expf(-gi));
                    float fv = 1.f / (1.f + expf(-gf));
                    float gv = tanhf(gg);
                    float ov = 1.f / (1.f + expf(-go));
                    size_t idx = (size_t)(rbase + r * 8) * HH + nglob;
                    float cn = fv * g_c[idx] + iv * gv;
                    g_c[idx] = cn;
                    float hv = ov * tanhf(cn);
                    __half hi = __float2half_rn(hv);
                    hh_o[idx] = hi;
                    hl_o[idx] = __float2half_rn(hv - __half2float(hi));
                }
            }
        }
        __threadfence();
        __syncthreads();
        bar_arrive((unsigned)t);
    }
}

// ---------------- final FC ------------------------------------------------------
__global__ __launch_bounds__(256) void fc_kernel(
    const float* __restrict__ fcW, const float* __restrict__ fcb, float* __restrict__ out) {
    int w = blockIdx.x * 8 + (threadIdx.x >> 5);
    int lane = threadIdx.x & 31;
    if (w >= BB * CC) return;
    int b = w / CC, c = w - b * CC;
    const __half* __restrict__ hh = g_hh[0] + (size_t)b * HH;   // TT even
    const __half* __restrict__ hl = g_hl[0] + (size_t)b * HH;
    const float* __restrict__ wr = fcW + (size_t)c * HH;
    float s = 0.f;
#pragma unroll 4
    for (int k = lane; k < HH; k += 32)
        s += (__half2float(hh[k]) + __half2float(hl[k])) * wr[k];
#pragma unroll
    for (int o = 16; o; o >>= 1) s += __shfl_down_sync(0xFFFFFFFFu, s, o);
    if (lane == 0) out[b * CC + c] = s + fcb[c];
}

extern "C" void kernel_launch(void* const* d_in, const int* in_sizes, int n_in,
                              void* d_out, int out_size) {
    const float* x   = (const float*)d_in[0];
    const float* Wih = (const float*)d_in[1];
    const float* Whh = (const float*)d_in[2];
    const float* bih = (const float*)d_in[3];
    const float* bhh = (const float*)d_in[4];
    const float* fcW = (const float*)d_in[5];
    const float* fcb = (const float*)d_in[6];
    float* out = (float*)d_out;

    cudaFuncSetAttribute(lstm_persist, cudaFuncAttributeMaxDynamicSharedMemorySize, SMEM_DYN);

    prep_w<<<(GG * KTOT + 255) / 256, 256>>>(Wih, Whh);
    prep_x<<<(TT * BB * II + 255) / 256, 256>>>(x);
    prep_misc<<<(BB * HH + 255) / 256, 256>>>(bih, bhh);
    lstm_persist<<<NCTA, NTHR, SMEM_DYN>>>();
    fc_kernel<<<(BB * CC + 7) / 8, 256>>>(fcW, fcb, out);
}

// round 8
// speedup vs baseline: 1.9412x; 1.2060x over previous
#include <cuda_runtime.h>
#include <cuda_fp16.h>
#include <cstdint>
#include <math.h>

#define BB 128
#define TT 512
#define II 256
#define HH 1024
#define GG 4096
#define CC 1000
#define KTOT 1280
#define NCHUNK 10          // K chunks of 128: chunks 0,1 = x (hi+lo), 2..9 = h (hi)
#define NCTA 128
#define NTHR 512

// SMEM layout (offsets from 128B-aligned dynamic base):
//   Whi [32][1280] fp16 swizzled, 2560B rows : 81920
//   A double buf: 2 x 64KB; each buf = [sub0: hi 16K | lo 16K][sub1: hi | lo]
//   (h chunks fill only the hi sub-regions)
#define W_HI 0u
#define A_BUF 81920u
#define ABUF_STRIDE 65536u
#define SMEM_DYN (81920 + 131072 + 256)

// ---------------- device globals (no dynamic alloc) ---------------------------
__device__ __align__(16) __half g_Wh[GG * KTOT];            // weights hi, permuted
__device__ __align__(16) __half g_xh[TT * BB * II];         // x hi, [t][m][k]
__device__ __align__(16) __half g_xl[TT * BB * II];         // x lo
__device__ __align__(16) __half g_hh[2][BB * HH];           // h fp16 ping-pong
__device__ float g_c[BB * HH];
__device__ float g_bs[GG];
__device__ unsigned g_bar_cnt;
__device__ unsigned g_bar_flag;

// ---------------- helpers ------------------------------------------------------
__device__ __forceinline__ uint32_t smem_u32(const void* p) {
    uint32_t a;
    asm("{ .reg .u64 t; cvta.to.shared.u64 t, %1; cvt.u32.u64 %0, t; }" : "=r"(a) : "l"(p));
    return a;
}
__device__ __forceinline__ void cp16(uint32_t saddr, const void* gaddr) {
    asm volatile("cp.async.cg.shared.global [%0], [%1], 16;" :: "r"(saddr), "l"(gaddr) : "memory");
}
__device__ __forceinline__ void ldsm4(uint32_t addr, uint32_t& r0, uint32_t& r1,
                                      uint32_t& r2, uint32_t& r3) {
    asm volatile("ldmatrix.sync.aligned.m8n8.x4.shared.b16 {%0,%1,%2,%3}, [%4];"
                 : "=r"(r0), "=r"(r1), "=r"(r2), "=r"(r3) : "r"(addr));
}
__device__ __forceinline__ void mma16816(float* c, const uint32_t* a, uint32_t b0, uint32_t b1) {
    asm volatile(
        "mma.sync.aligned.m16n8k16.row.col.f32.f16.f16.f32 "
        "{%0,%1,%2,%3}, {%4,%5,%6,%7}, {%8,%9}, {%0,%1,%2,%3};"
        : "+f"(c[0]), "+f"(c[1]), "+f"(c[2]), "+f"(c[3])
        : "r"(a[0]), "r"(a[1]), "r"(a[2]), "r"(a[3]), "r"(b0), "r"(b1));
}

// ---------------- prep kernels -------------------------------------------------
// Stored row r = nb*32 + hc*4 + q  <->  original row q*H + nb*8 + hc.
__global__ void prep_w(const float* __restrict__ Wih, const float* __restrict__ Whh) {
    int idx = blockIdx.x * blockDim.x + threadIdx.x;
    if (idx >= GG * KTOT) return;
    int r = idx / KTOT, k = idx - r * KTOT;
    int nb = r >> 5, j = r & 31, hc = j >> 2, q = j & 3;
    int orig = q * HH + nb * 8 + hc;
    float v = (k < II) ? Wih[(size_t)orig * II + k] : Whh[(size_t)orig * HH + (k - II)];
    g_Wh[idx] = __float2half_rn(v);
}

__global__ void prep_x(const float* __restrict__ x) {
    int idx = blockIdx.x * blockDim.x + threadIdx.x;
    if (idx >= TT * BB * II) return;
    int t = idx / (BB * II);
    int rem = idx - t * (BB * II);
    int m = rem / II, k = rem - m * II;
    float v = x[((size_t)m * TT + t) * II + k];
    __half hi = __float2half_rn(v);
    g_xh[idx] = hi;
    g_xl[idx] = __float2half_rn(v - __half2float(hi));
}

__global__ void prep_misc(const float* __restrict__ bih, const float* __restrict__ bhh) {
    int i = blockIdx.x * blockDim.x + threadIdx.x;
    if (i < BB * HH) {
        g_hh[0][i] = __float2half_rn(0.f);
        g_c[i] = 0.f;
    }
    if (i < GG) g_bs[i] = bih[i] + bhh[i];
    if (i == 0) { g_bar_cnt = 0u; g_bar_flag = 0u; }
}

// ---------------- grid barrier (all 128 CTAs resident, one wave) ---------------
__device__ __forceinline__ void bar_arrive(unsigned step) {
    if (threadIdx.x == 0) {
        unsigned v;
        asm volatile("atom.release.gpu.global.add.u32 %0, [%1], 1;"
                     : "=r"(v) : "l"(&g_bar_cnt) : "memory");
        if (v == NCTA * (step + 1) - 1) {
            asm volatile("st.release.gpu.global.u32 [%0], %1;"
                         :: "l"(&g_bar_flag), "r"(step + 1) : "memory");
        }
    }
}
__device__ __forceinline__ void bar_wait(unsigned step) {   // wait flag >= step
    if (threadIdx.x == 0) {
        unsigned f;
        while (true) {
            asm volatile("ld.acquire.gpu.global.u32 %0, [%1];"
                         : "=r"(f) : "l"(&g_bar_flag) : "memory");
            if (f >= step) break;
            __nanosleep(64);
        }
    }
    __syncthreads();
}

// ---------------- persistent LSTM kernel ---------------------------------------
// 128 CTAs x 512 thr (16 warps = 8m x 2n). CTA: M=128, N=32 gate cols = 8 h-cols.
// Warp tile 16x16 -> acc[2 nf][4].
// Numerics: gates = (xhi+xlo) @ Whi  +  h_fp16 @ Whi   (fp32 accum).
__global__ __launch_bounds__(NTHR, 1) void lstm_persist() {
    extern __shared__ __align__(16) char dsm_raw[];
    const uint32_t dbase = (smem_u32(dsm_raw) + 127) & ~127u;

    const int tid = threadIdx.x;
    const int wid = tid >> 5, lid = tid & 31;
    const int wm = wid >> 1, wn = wid & 1;      // 8 m-groups x 2 n-groups
    const int nb = blockIdx.x;
    const int mi = lid >> 3, lr = lid & 7;

    // ---- load this CTA's weight slice (hi only) into SMEM once ----
    for (int s = 0; s < 10; s++) {
        int idx = tid + NTHR * s;               // 0..5119
        int row = idx / 160, seg = idx - row * 160;
        size_t go = (size_t)(nb * 32 + row) * KTOT + seg * 8;
        uint32_t so = (uint32_t)row * 2560u + (uint32_t)((seg ^ (row & 7)) << 4);
        cp16(dbase + W_HI + so, g_Wh + go);
    }
    asm volatile("cp.async.commit_group;" ::: "memory");

    const int lq = lid & 3;
    const bool hasIF = (lq & 1) == 0;
    const int hcl = lq >> 1;

    // lane-fixed ldsm addressing pieces
    const int arow = wm * 16 + ((mi & 1) << 3) + lr;
    const uint32_t aoff = (uint32_t)arow * 128u;
    const int axor = arow & 7;
    const int brow = wn * 16 + ((mi >> 1) << 3) + lr;
    const uint32_t bbase0 = dbase + W_HI + (uint32_t)brow * 2560u;
    const int bxor = brow & 7;

#pragma unroll 1
    for (int t = 0; t < TT; t++) {
        const __half* __restrict__ hsh = g_hh[t & 1];
        const __half* __restrict__ xsh = g_xh + (size_t)t * (BB * II);
        const __half* __restrict__ xsl = g_xl + (size_t)t * (BB * II);

        // A chunk loader. x chunks (kc<2): hi+lo = 4096 cp16. h chunks: hi = 2048.
        auto load_chunk = [&](int kc) {
            const uint32_t bofs = A_BUF + (uint32_t)(kc & 1) * ABUF_STRIDE;
            const int k0 = kc * 128;
            if (kc < 2) {
#pragma unroll
                for (int s = 0; s < 8; s++) {
                    int idx = tid + NTHR * s;       // 0..4095
                    int reg = idx >> 11;            // 0 hi, 1 lo
                    int w = idx & 2047;
                    int row = w >> 4, seg = w & 15;
                    uint32_t sa = dbase + bofs + (uint32_t)(seg >> 3) * 32768u
                                + (uint32_t)reg * 16384u
                                + (uint32_t)row * 128u
                                + (uint32_t)(((seg & 7) ^ (row & 7)) << 4);
                    const __half* g = (reg ? xsl : xsh) + (size_t)row * II + k0 + seg * 8;
                    cp16(sa, g);
                }
            } else {
#pragma unroll
                for (int s = 0; s < 4; s++) {
                    int idx = tid + NTHR * s;       // 0..2047 (hi only)
                    int row = idx >> 4, seg = idx & 15;
                    uint32_t sa = dbase + bofs + (uint32_t)(seg >> 3) * 32768u
                                + (uint32_t)row * 128u
                                + (uint32_t)(((seg & 7) ^ (row & 7)) << 4);
                    const __half* g = hsh + (size_t)row * HH + (k0 - II) + seg * 8;
                    cp16(sa, g);
                }
            }
            asm volatile("cp.async.commit_group;" ::: "memory");
        };

        float acc[2][4];
#pragma unroll
        for (int a = 0; a < 2; a++)
#pragma unroll
            for (int i = 0; i < 4; i++) acc[a][i] = 0.f;

        load_chunk(0);          // x
        load_chunk(1);          // x

#pragma unroll 1
        for (int kc = 0; kc < NCHUNK; kc++) {
            if (kc + 1 < NCHUNK) asm volatile("cp.async.wait_group 1;" ::: "memory");
            else                 asm volatile("cp.async.wait_group 0;" ::: "memory");
            __syncthreads();

            const uint32_t abase = dbase + A_BUF + (uint32_t)(kc & 1) * ABUF_STRIDE;
            const bool haslo = (kc < 2);

#pragma unroll
            for (int ks = 0; ks < 8; ks++) {
                // A frag m16k16 (hi; lo only for x chunks)
                uint32_t ah[4];
                uint32_t ad;
                {
                    int ksega = (ks & 3) * 2 + (mi >> 1);
                    ad = abase + (uint32_t)(ks >> 2) * 32768u + aoff
                       + (uint32_t)((ksega ^ axor) << 4);
                    ldsm4(ad, ah[0], ah[1], ah[2], ah[3]);
                }
                // B frag n16k16 (hi only) from resident W
                uint32_t bh[4];
                {
                    int kseg = kc * 16 + ks * 2 + (mi & 1);
                    uint32_t bd = bbase0 + (uint32_t)((kseg ^ bxor) << 4);
                    ldsm4(bd, bh[0], bh[1], bh[2], bh[3]);
                }
                mma16816(acc[0], ah, bh[0], bh[1]);
                mma16816(acc[1], ah, bh[2], bh[3]);
                if (haslo) {
                    uint32_t al[4];
                    ldsm4(ad + 16384u, al[0], al[1], al[2], al[3]);
                    mma16816(acc[0], al, bh[0], bh[1]);
                    mma16816(acc[1], al, bh[2], bh[3]);
                }
            }
            __syncthreads();
            if (kc + 2 < NCHUNK) {
                if (kc + 2 == 2) bar_wait((unsigned)t);   // h(t) ready before 1st h chunk
                load_chunk(kc + 2);
            }
        }

        // ---- epilogue: bias + LSTM update, write h(t+1) as fp16 ----
        __half* __restrict__ hh_o = g_hh[(t + 1) & 1];
        const int rbase = wm * 16 + (lid >> 2);
#pragma unroll
        for (int nf = 0; nf < 2; nf++) {
            const int nglob = nb * 8 + wn * 4 + nf * 2 + hcl;
            const float bias0 = g_bs[(hasIF ? 0 : 2) * HH + nglob];
            const float bias1 = g_bs[(hasIF ? 1 : 3) * HH + nglob];
            float d0 = acc[nf][0] + bias0;
            float d1 = acc[nf][1] + bias1;
            float d2 = acc[nf][2] + bias0;
            float d3 = acc[nf][3] + bias1;
            float e0 = __shfl_xor_sync(0xFFFFFFFFu, d0, 1);
            float e1 = __shfl_xor_sync(0xFFFFFFFFu, d1, 1);
            float e2 = __shfl_xor_sync(0xFFFFFFFFu, d2, 1);
            float e3 = __shfl_xor_sync(0xFFFFFFFFu, d3, 1);
            if (hasIF) {
#pragma unroll
                for (int r = 0; r < 2; r++) {
                    float gi = r ? d2 : d0, gf = r ? d3 : d1;
                    float gg = r ? e2 : e0, go = r ? e3 : e1;
                    float iv = 1.f / (1.f + expf(-gi));
                    float fv = 1.f / (1.f + expf(-gf));
                    float gv = tanhf(gg);
                    float ov = 1.f / (1.f + expf(-go));
                    size_t idx = (size_t)(rbase + r * 8) * HH + nglob;
                    float cn = fv * g_c[idx] + iv * gv;
                    g_c[idx] = cn;
                    float hv = ov * tanhf(cn);
                    hh_o[idx] = __float2half_rn(hv);
                }
            }
        }
        __threadfence();
        __syncthreads();
        bar_arrive((unsigned)t);
    }
}

// ---------------- final FC ------------------------------------------------------
__global__ __launch_bounds__(256) void fc_kernel(
    const float* __restrict__ fcW, const float* __restrict__ fcb, float* __restrict__ out) {
    int w = blockIdx.x * 8 + (threadIdx.x >> 5);
    int lane = threadIdx.x & 31;
    if (w >= BB * CC) return;
    int b = w / CC, c = w - b * CC;
    const __half* __restrict__ hh = g_hh[0] + (size_t)b * HH;   // TT even
    const float* __restrict__ wr = fcW + (size_t)c * HH;
    float s = 0.f;
#pragma unroll 4
    for (int k = lane; k < HH; k += 32)
        s += __half2float(hh[k]) * wr[k];
#pragma unroll
    for (int o = 16; o; o >>= 1) s += __shfl_down_sync(0xFFFFFFFFu, s, o);
    if (lane == 0) out[b * CC + c] = s + fcb[c];
}

extern "C" void kernel_launch(void* const* d_in, const int* in_sizes, int n_in,
                              void* d_out, int out_size) {
    const float* x   = (const float*)d_in[0];
    const float* Wih = (const float*)d_in[1];
    const float* Whh = (const float*)d_in[2];
    const float* bih = (const float*)d_in[3];
    const float* bhh = (const float*)d_in[4];
    const float* fcW = (const float*)d_in[5];
    const float* fcb = (const float*)d_in[6];
    float* out = (float*)d_out;

    cudaFuncSetAttribute(lstm_persist, cudaFuncAttributeMaxDynamicSharedMemorySize, SMEM_DYN);

    prep_w<<<(GG * KTOT + 255) / 256, 256>>>(Wih, Whh);
    prep_x<<<(TT * BB * II + 255) / 256, 256>>>(x);
    prep_misc<<<(BB * HH + 255) / 256, 256>>>(bih, bhh);
    lstm_persist<<<NCTA, NTHR, SMEM_DYN>>>();
    fc_kernel<<<(BB * CC + 7) / 8, 256>>>(fcW, fcb, out);
}